// round 12
// baseline (speedup 1.0000x reference)
#include <cuda_runtime.h>
#include <math.h>
#include <stdint.h>

// Problem constants (match reference)
#define N_INPUTS 2048
#define UNITS    2048
#define L        8
#define FANIN    4096
#define TOTAL    (N_INPUTS + L * UNITS)   // 18432

// Decomposition: block owns 8 units across ALL rows. No split-K partials.
#define NBLK     256                      // co-resident (>=2 blocks/SM, 148 SMs)
#define TPB      256
#define NBAR     7                        // barriers between the 8 layers

// Scratch (device globals: allocation-free per harness rules)
__device__ float g_state[TOTAL];          // shared "outputs" vector
__device__ int   g_bar[NBAR];

__global__ void init_kernel(const float* __restrict__ x) {
    int i = blockIdx.x * blockDim.x + threadIdx.x;
    if (i < TOTAL) g_state[i] = (i < N_INPUTS) ? x[i] : 0.0f;
    if (i < NBAR)  g_bar[i] = 0;
}

__device__ __forceinline__ void bar_arrive(int* p) {
    asm volatile("red.release.gpu.global.add.s32 [%0], 1;" :: "l"(p) : "memory");
}
__device__ __forceinline__ int ld_acq(const int* p) {
    int v; asm volatile("ld.acquire.gpu.global.s32 %0, [%1];" : "=r"(v) : "l"(p) : "memory");
    return v;
}
__device__ __forceinline__ void pf_l2(const void* p) {
    asm volatile("prefetch.global.L2 [%0];" :: "l"(p));
}

// Thread layout: kpart = tid>>1 owns rows [32*kpart, 32*kpart+32);
// upart = tid&1 owns units [8*bid + 4*upart, +4) as one float4 slice.
// Lane pairs (2*kpart, 2*kpart+1) cover one full 32B sector of W per row:
// every sector fetched exactly once chip-wide, fully used.
__global__ __launch_bounds__(TPB, 2) void net_kernel(
    const float* __restrict__ Ws,        // [L, FANIN, UNITS]
    const int*   __restrict__ node_inds, // [L, FANIN]
    const float* __restrict__ bs,        // [L, UNITS]
    float*       __restrict__ out)       // [UNITS]
{
    __shared__ float4 red[TPB];

    const int tid   = threadIdx.x;
    const int bid   = blockIdx.x;
    const int upart = tid & 1;
    const int kpart = tid >> 1;
    const int kbase = kpart * 32;
    const int u0    = bid * 8 + upart * 4;     // this thread's 4 units

    float4 acc = make_float4(0.f, 0.f, 0.f, 0.f);

    // ---- layer 0 bulk: everything live (ind < 2048) is published by init ----
    {
        const int4*  iv = reinterpret_cast<const int4*>(node_inds + kbase);
        const float* W0 = Ws;
        #pragma unroll
        for (int jv = 0; jv < 8; ++jv) {
            const int4 q = iv[jv];
            const int kk = kbase + jv * 4;
            const int idx[4] = {q.x, q.y, q.z, q.w};
            #pragma unroll
            for (int c = 0; c < 4; ++c) {
                const int ind = idx[c];
                if (ind < 2048) {
                    const float s = g_state[ind];
                    const float4 w = *reinterpret_cast<const float4*>(
                        W0 + (size_t)(kk + c) * UNITS + u0);
                    acc.x = fmaf(s, w.x, acc.x);
                    acc.y = fmaf(s, w.y, acc.y);
                    acc.z = fmaf(s, w.z, acc.z);
                    acc.w = fmaf(s, w.w, acc.w);
                }
            }
        }
    }

    for (int i = 0; i < L; ++i) {
        // ---- serial window: deferred rows of layer i (segment i only) ----
        // Their multipliers (g_state segment i) were published at bar_{i-1};
        // their W lines were pf_l2'd during last phase's overlap window.
        if (i > 0) {
            const int dlo = i * 2048, dhi = dlo + 2048;
            const int4*  iv = reinterpret_cast<const int4*>(
                node_inds + i * FANIN + kbase);
            const float* Wi = Ws + (size_t)i * FANIN * UNITS;
            #pragma unroll
            for (int jv = 0; jv < 8; ++jv) {
                const int4 q = iv[jv];
                const int kk = kbase + jv * 4;
                const int idx[4] = {q.x, q.y, q.z, q.w};
                #pragma unroll
                for (int c = 0; c < 4; ++c) {
                    const int ind = idx[c];
                    if (ind >= dlo && ind < dhi) {
                        const float s = g_state[ind];
                        const float4 w = *reinterpret_cast<const float4*>(
                            Wi + (size_t)(kk + c) * UNITS + u0);
                        acc.x = fmaf(s, w.x, acc.x);
                        acc.y = fmaf(s, w.y, acc.y);
                        acc.z = fmaf(s, w.z, acc.z);
                        acc.w = fmaf(s, w.w, acc.w);
                    }
                }
            }
        }

        // ---- intra-block tree reduce over kparts (fixed order, smem) ----
        red[tid] = acc;
        __syncthreads();
        #pragma unroll
        for (int s = TPB / 2; s >= 2; s >>= 1) {   // s even -> same upart
            if (tid < s) {
                float4 a = red[tid], b = red[tid + s];
                a.x += b.x; a.y += b.y; a.z += b.z; a.w += b.w;
                red[tid] = a;
            }
            __syncthreads();
        }

        // ---- bias + tanh + publish segment i+1 (and out on last layer) ----
        if (tid < 2) {
            float4 r = red[tid];
            const float4 bb = *reinterpret_cast<const float4*>(
                bs + i * UNITS + bid * 8 + tid * 4);
            r.x = tanhf(r.x + bb.x);
            r.y = tanhf(r.y + bb.y);
            r.z = tanhf(r.z + bb.z);
            r.w = tanhf(r.w + bb.w);
            *reinterpret_cast<float4*>(g_state + (i + 1) * 2048 + bid * 8 + tid * 4) = r;
            if (i == L - 1)
                *reinterpret_cast<float4*>(out + bid * 8 + tid * 4) = r;
        }
        __syncthreads();                 // order tid1's store before tid0's arrive

        if (i == L - 1) break;

        if (tid == 0) bar_arrive(&g_bar[i]);

        // ---- overlap window: bulk-stream layer i+1 + prefetch its deferred ----
        // Published segments: [0, (i+1)*2048) (bar_{i-1} passed; our own seg i+1
        // values are NOT read here -- they are exactly the deferred set).
        const int plim = (i + 1) * 2048;
        const int dhi2 = plim + 2048;
        float4 nacc = make_float4(0.f, 0.f, 0.f, 0.f);
        {
            const int4*  iv = reinterpret_cast<const int4*>(
                node_inds + (i + 1) * FANIN + kbase);
            const float* Wn = Ws + (size_t)(i + 1) * FANIN * UNITS;
            #pragma unroll
            for (int jv = 0; jv < 8; ++jv) {
                const int4 q = iv[jv];
                const int kk = kbase + jv * 4;
                const int idx[4] = {q.x, q.y, q.z, q.w};
                #pragma unroll
                for (int c = 0; c < 4; ++c) {
                    const int ind = idx[c];
                    const float* wp = Wn + (size_t)(kk + c) * UNITS + u0;
                    if (ind < plim) {
                        const float s = g_state[ind];
                        const float4 w = *reinterpret_cast<const float4*>(wp);
                        nacc.x = fmaf(s, w.x, nacc.x);
                        nacc.y = fmaf(s, w.y, nacc.y);
                        nacc.z = fmaf(s, w.z, nacc.z);
                        nacc.w = fmaf(s, w.w, nacc.w);
                    } else if (ind < dhi2) {
                        pf_l2(wp);       // deferred row: warm L2 for next serial
                    }
                }
            }
        }

        // ---- wait: segment i+1 fully published by all blocks ----
        if (tid == 0) {
            while (ld_acq(&g_bar[i]) < NBLK) { __nanosleep(16); }
        }
        __syncthreads();

        acc = nacc;
    }
}

extern "C" void kernel_launch(void* const* d_in, const int* in_sizes, int n_in,
                              void* d_out, int out_size) {
    const float* x         = (const float*)d_in[0];  // [2048] f32
    const int*   node_inds = (const int*)  d_in[1];  // [L, FANIN] i32
    const float* Ws        = (const float*)d_in[2];  // [L, FANIN, UNITS] f32
    const float* bs        = (const float*)d_in[3];  // [L, UNITS] f32
    float*       out       = (float*)d_out;          // [2048] f32

    init_kernel<<<(TOTAL + 255) / 256, 256>>>(x);
    net_kernel<<<NBLK, TPB>>>(Ws, node_inds, bs, out);
}

// round 13
// speedup vs baseline: 2.9376x; 2.9376x over previous
#include <cuda_runtime.h>
#include <math.h>
#include <stdint.h>

// Problem constants (match reference)
#define N_INPUTS 2048
#define UNITS    2048
#define L        8
#define FANIN    4096
#define TOTAL    (N_INPUTS + L * UNITS)   // 18432

// Persistent-kernel decomposition (R10 base: best measured)
#define NBLK     256                      // co-resident (>=2 blocks/SM, 148 SMs)
#define TPB      256
#define KSPLIT   128                      // k-chunks per layer
#define KCHUNK   (FANIN / KSPLIT)         // 32 rows per chunk
#define NBAR     L

// Scratch (device globals: allocation-free per harness rules)
__device__ float g_state[TOTAL];                    // shared "outputs" vector
__device__ float g_pt[2][UNITS * KSPLIT];           // TRANSPOSED partials [u][s]
__device__ int   g_bar[NBAR];

__global__ void init_kernel(const float* __restrict__ x) {
    int i = blockIdx.x * blockDim.x + threadIdx.x;
    if (i < TOTAL) g_state[i] = (i < N_INPUTS) ? x[i] : 0.0f;
    if (i < NBAR)  g_bar[i] = 0;
}

__device__ __forceinline__ float ldcg_f(const float* p) {
    float v; asm volatile("ld.global.cg.f32 %0, [%1];" : "=f"(v) : "l"(p)); return v;
}
__device__ __forceinline__ float4 ldcg_f4(const float4* p) {
    float4 v;
    asm volatile("ld.global.cg.v4.f32 {%0,%1,%2,%3}, [%4];"
                 : "=f"(v.x), "=f"(v.y), "=f"(v.z), "=f"(v.w) : "l"(p));
    return v;
}
__device__ __forceinline__ void bar_arrive(int* p) {
    asm volatile("red.release.gpu.global.add.s32 [%0], 1;" :: "l"(p) : "memory");
}
__device__ __forceinline__ int ld_acq(const int* p) {
    int v; asm volatile("ld.acquire.gpu.global.s32 %0, [%1];" : "=r"(v) : "l"(p) : "memory");
    return v;
}
__device__ __forceinline__ void pf_l2(const void* p) {
    asm volatile("prefetch.global.L2 [%0];" :: "l"(p));
}

// Coalesced reduction of one unit's KSPLIT partials from the transposed
// buffer: warp reads 32 consecutive float4s (512B), fixed order -> deterministic.
__device__ __forceinline__ float reduce_t(const float* buf, int u, int lane) {
    const float4 v = ldcg_f4(reinterpret_cast<const float4*>(buf) + u * (KSPLIT / 4) + lane);
    float a = (v.x + v.y) + (v.z + v.w);
    #pragma unroll
    for (int off = 16; off > 0; off >>= 1) a += __shfl_xor_sync(0xFFFFFFFFu, a, off);
    return a;
}

// Group-of-8 batched FMA stream: 8 independent LDG.128s issued back-to-back
// (fixed-size unrolled loop -> ptxas front-batches them into flight), then
// the 32 FFMAs. Doubles per-thread MLP vs the rolled loop.
__device__ __forceinline__ void stream_rows(
    const float4* __restrict__ W4, const int* __restrict__ liv,
    const float* __restrict__ lval, int n, float4& acc)
{
    int j = 0;
    for (; j + 8 <= n; j += 8) {
        float4 w[8];
        float  s[8];
        #pragma unroll
        for (int t = 0; t < 8; ++t) {
            w[t] = W4[(size_t)liv[j + t] * 512];
            s[t] = lval[j + t];
        }
        #pragma unroll
        for (int t = 0; t < 8; ++t) {
            acc.x = fmaf(s[t], w[t].x, acc.x);
            acc.y = fmaf(s[t], w[t].y, acc.y);
            acc.z = fmaf(s[t], w[t].z, acc.z);
            acc.w = fmaf(s[t], w[t].w, acc.w);
        }
    }
    for (; j < n; ++j) {
        const float  s = lval[j];
        const float4 w = W4[(size_t)liv[j] * 512];
        acc.x = fmaf(s, w.x, acc.x);
        acc.y = fmaf(s, w.y, acc.y);
        acc.z = fmaf(s, w.z, acc.z);
        acc.w = fmaf(s, w.w, acc.w);
    }
}

// Pipelined persistent kernel (R10 schedule). Block bid: kc=bid>>1, uh=bid&1.
__global__ __launch_bounds__(TPB, 2) void net_kernel(
    const float* __restrict__ Ws,        // [L, FANIN, UNITS]
    const int*   __restrict__ node_inds, // [L, FANIN]
    const float* __restrict__ bs,        // [L, UNITS]
    float*       __restrict__ out)       // [UNITS]
{
    __shared__ int   sind[KCHUNK];
    __shared__ int   liv[KCHUNK];
    __shared__ int   dliv[KCHUNK];
    __shared__ float lval[KCHUNK];
    __shared__ int   nliv, ndef;

    const int tid   = threadIdx.x;
    const int bid   = blockIdx.x;
    const int kc    = bid >> 1;
    const int uh    = bid & 1;
    const int warp  = tid >> 5;
    const int lane  = tid & 31;
    const int myu   = bid * 8 + warp;        // this warp's finalize unit
    const int ubase = uh * 1024 + 4 * tid;   // this thread's 4 units

    float4 acc = make_float4(0.f, 0.f, 0.f, 0.f);
    int plim_prev = 0;

    for (int i = 0; i < L; ++i) {
        const int llim = (i + 1) * 2048;
        const int slim = i * 2048;
        const int pb   = (i - 1) & 1;
        const int* inds = node_inds + i * FANIN + kc * KCHUNK;

        // ---- finalize layer i-1 -> g_state segment i (published at bar_i) ----
        if (i > 0) {
            const float a = reduce_t(g_pt[pb], myu, lane);
            if (lane == 0) g_state[slim + myu] = tanhf(a + bs[(i - 1) * UNITS + myu]);
        }

        // ---- deterministic compaction of deferred live rows ----
        if (warp == 0) {
            const int ind = inds[lane];
            sind[lane] = ind;
            const bool d = (ind >= plim_prev) && (ind < llim);
            const unsigned m = __ballot_sync(0xFFFFFFFFu, d);
            if (d) liv[__popc(m & ((1u << lane) - 1))] = lane;
            if (lane == 0) nliv = __popc(m);
        }
        __syncthreads();
        const int n = nliv;

        // ---- fill deferred values (g_state read or on-the-fly reduce) ----
        for (int j = warp; j < n; j += 8) {
            const int k   = liv[j];
            const int ind = sind[k];
            float v;
            if (i > 0 && ind >= slim) {
                const int u = ind - slim;
                const float a = reduce_t(g_pt[pb], u, lane);
                v = tanhf(a + bs[(i - 1) * UNITS + u]);
            } else {
                v = (lane == 0) ? ldcg_f(&g_state[ind]) : 0.0f;
            }
            if (lane == 0) lval[j] = v;
        }
        __syncthreads();

        // ---- stream deferred W rows (L2-hot from last phase's prefetch) ----
        const float4* W4 = reinterpret_cast<const float4*>(Ws + (size_t)i * FANIN * UNITS)
                         + (size_t)kc * KCHUNK * 512 + uh * 256 + tid;
        stream_rows(W4, liv, lval, n, acc);

        // ---- store transposed partials for layer i ----
        float* pt = g_pt[i & 1];
        pt[(size_t)(ubase + 0) * KSPLIT + kc] = acc.x;
        pt[(size_t)(ubase + 1) * KSPLIT + kc] = acc.y;
        pt[(size_t)(ubase + 2) * KSPLIT + kc] = acc.z;
        pt[(size_t)(ubase + 3) * KSPLIT + kc] = acc.w;
        __syncthreads();

        if (tid == 0) bar_arrive(&g_bar[i]);

        // ---- overlap window: prefetch deferred W + bulk-stream layer i+1 ----
        const int plim = (i == 0) ? 2048 : slim;
        float4 nacc = make_float4(0.f, 0.f, 0.f, 0.f);
        if (i + 1 < L) {
            const int nlim = llim + 2048;
            const int* ninds = node_inds + (i + 1) * FANIN + kc * KCHUNK;
            if (warp == 0) {
                const int ind = ninds[lane];
                sind[lane] = ind;
                const bool lv = (ind < nlim);
                const bool p  = (ind < plim);
                const unsigned mb = __ballot_sync(0xFFFFFFFFu, p);
                const unsigned md = __ballot_sync(0xFFFFFFFFu, lv && !p);
                if (p)        liv [__popc(mb & ((1u << lane) - 1))] = lane;
                if (lv && !p) dliv[__popc(md & ((1u << lane) - 1))] = lane;
                if (lane == 0) { nliv = __popc(mb); ndef = __popc(md); }
            }
            __syncthreads();
            const int n2 = nliv;
            const int nd = ndef;

            // Prefetch deferred W rows of layer i+1 into L2 FIRST.
            const float* Wn = Ws + (size_t)(i + 1) * FANIN * UNITS
                            + (size_t)kc * KCHUNK * UNITS + uh * 1024;
            for (int j = warp; j < nd; j += 8) {
                const char* p = (const char*)(Wn + (size_t)dliv[j] * UNITS) + lane * 128;
                pf_l2(p);
            }

            if (tid < KCHUNK && tid < n2) {
                lval[tid] = ldcg_f(&g_state[sind[liv[tid]]]);
            }
            __syncthreads();

            const float4* W4n = reinterpret_cast<const float4*>(
                                    Ws + (size_t)(i + 1) * FANIN * UNITS)
                              + (size_t)kc * KCHUNK * 512 + uh * 256 + tid;
            stream_rows(W4n, liv, lval, n2, nacc);
        }

        // ---- wait for all blocks (partials_i + segment i published) ----
        if (tid == 0) {
            while (ld_acq(&g_bar[i]) < NBLK) { __nanosleep(16); }
        }
        __syncthreads();

        acc = nacc;
        plim_prev = plim;
    }

    // ---- final output: finalize layer L-1 ----
    {
        const float a = reduce_t(g_pt[(L - 1) & 1], myu, lane);
        if (lane == 0) out[myu] = tanhf(a + bs[(L - 1) * UNITS + myu]);
    }
}

extern "C" void kernel_launch(void* const* d_in, const int* in_sizes, int n_in,
                              void* d_out, int out_size) {
    const float* x         = (const float*)d_in[0];  // [2048] f32
    const int*   node_inds = (const int*)  d_in[1];  // [L, FANIN] i32
    const float* Ws        = (const float*)d_in[2];  // [L, FANIN, UNITS] f32
    const float* bs        = (const float*)d_in[3];  // [L, UNITS] f32
    float*       out       = (float*)d_out;          // [2048] f32

    init_kernel<<<(TOTAL + 255) / 256, 256>>>(x);
    net_kernel<<<NBLK, TPB>>>(Ws, node_inds, bs, out);
}